// round 13
// baseline (speedup 1.0000x reference)
#include <cuda_runtime.h>
#include <math.h>
#include <stdint.h>

#define BATCH 1024
#define SEQT 128
#define HIDDEN 512
#define HH (HIDDEN*HIDDEN)
#define BH (BATCH*HIDDEN)
#define NLAYER 4
#define PRED 10
#define INDIM 6
#define OUTDIM 6
#define NT (BATCH*SEQT)
#define ENC_ELEMS (NT*HIDDEN)
#define PADK 20
#define NSTAGE 4
#define STAGE_WORDS (2*128*PADK)
#define SMEM_BYTES (NSTAGE*STAGE_WORDS*4)

// ---------------- scratch (device globals; no allocation allowed) ----------------
__device__ float g_h[NLAYER*2*BH];            // encoder hidden ping-pong [layer][parity][B*H] (tf32-rounded)
__device__ float g_hd[2*NLAYER*BH];           // decoder hidden ping-pong (tf32-rounded)
__device__ float g_part[4*BH];                // split-K partials
__device__ float g_decout[BATCH*PRED*HIDDEN]; // decoder outputs for FC
__device__ float g_wr[15*HH];                 // tf32-rounded weights: [eWih(3)][eWhh(4)][dWih(4)][dWhh(4)]

// ---------------- tf32 / cp.async helpers ----------------
__device__ __forceinline__ unsigned cvt_tf32(float v){
    unsigned r; asm("cvt.rna.tf32.f32 %0, %1;" : "=r"(r) : "f"(v)); return r;
}
__device__ __forceinline__ float round_tf32f(float v){
    return __uint_as_float(cvt_tf32(v));
}
__device__ __forceinline__ void mma_tf32(float* d, const unsigned* a, const unsigned* b){
    asm volatile(
        "mma.sync.aligned.m16n8k8.row.col.f32.tf32.tf32.f32 "
        "{%0,%1,%2,%3}, {%4,%5,%6,%7}, {%8,%9}, {%0,%1,%2,%3};"
        : "+f"(d[0]), "+f"(d[1]), "+f"(d[2]), "+f"(d[3])
        : "r"(a[0]), "r"(a[1]), "r"(a[2]), "r"(a[3]), "r"(b[0]), "r"(b[1]));
}
__device__ __forceinline__ void cp_async16(uint32_t saddr, const void* gptr){
    asm volatile("cp.async.cg.shared.global [%0], [%1], 16;" :: "r"(saddr), "l"(gptr));
}
__device__ __forceinline__ void cp_commit(){
    asm volatile("cp.async.commit_group;");
}
template<int N> __device__ __forceinline__ void cp_wait(){
    asm volatile("cp.async.wait_group %0;" :: "n"(N));
}
__device__ __forceinline__ uint32_t smem_addr_u32(const void* p){
    uint32_t a;
    asm("{ .reg .u64 t; cvta.to.shared.u64 t, %1; cvt.u32.u64 %0, t; }" : "=r"(a) : "l"(p));
    return a;
}

// ---------------- MUFU-free tanh ----------------
__device__ __forceinline__ float fast_tanh(float x){
    float cx = fminf(fmaxf(x, -9.5f), 9.5f);
    float z  = cx * 2.8853900818f;               // 2x * log2(e)
    float y  = z + 12582912.0f;                  // round to nearest int
    int   n  = __float_as_int(y) - 0x4B400000;
    float f  = z - (y - 12582912.0f);            // [-0.5, 0.5]
    float t = 1.5252733e-05f;
    t = fmaf(t, f, 1.5403530e-04f);
    t = fmaf(t, f, 1.3333558e-03f);
    t = fmaf(t, f, 9.6181291e-03f);
    t = fmaf(t, f, 5.5504109e-02f);
    t = fmaf(t, f, 2.4022651e-01f);
    t = fmaf(t, f, 6.9314718e-01f);
    t = t * f;                                   // 2^f - 1
    float s   = __int_as_float((n + 127) << 23);
    float em1 = fmaf(s, t, s - 1.0f);            // e^{2x} - 1
    float ep1 = em1 + 2.0f;
    float r = __int_as_float(0x7EF311C3 - __float_as_int(ep1));
    r = r * fmaf(-ep1, r, 2.0f);
    r = r * fmaf(-ep1, r, 2.0f);
    r = r * fmaf(-ep1, r, 2.0f);
    return em1 * r;
}

// ---------------- fused weight pre-round: g_wr = tf32(all 15 matrices) ----------------
__global__ void round_weights_all(const float4* __restrict__ s0, const float4* __restrict__ s1,
                                  const float4* __restrict__ s2, const float4* __restrict__ s3,
                                  float4* __restrict__ dst)
{
    int i = blockIdx.x*blockDim.x + threadIdx.x;     // over 15*HH/4
    const int n1 = 3*HH/4, n2 = 7*HH/4, n3 = 11*HH/4, nT = 15*HH/4;
    if (i >= nT) return;
    const float4* s; int off;
    if (i < n1)      { s = s0; off = i; }
    else if (i < n2) { s = s1; off = i - n1; }
    else if (i < n3) { s = s2; off = i - n2; }
    else             { s = s3; off = i - n3; }
    float4 v = s[off];
    v.x = round_tf32f(v.x); v.y = round_tf32f(v.y);
    v.z = round_tf32f(v.z); v.w = round_tf32f(v.w);
    dst[i] = v;
}

// ---------------- tf32 GEMM pass: cp.async stages + register-pipelined fragments ----------------
// acc += A[bm:bm+128, kb:ke] @ W[bn:bn+128, kb:ke]^T ; A, W tf32-pre-rounded.
// 16 warps, warp tile 32x32. MMAs of chunk c consume frags loaded at iteration c-1:
// tensor pipe never waits on this iteration's LDS.
__device__ __forceinline__ void gemm_tf32(
    const float* __restrict__ A, const float* __restrict__ W,
    int kb, int ke, int bm, int bn, int tid,
    unsigned* sm, float (*d)[4][4])
{
    int rowL = tid >> 2;              // 0..127
    int koff = (tid & 3) << 2;        // 0,4,8,12
    int lane = tid & 31;
    int q = lane >> 2, r = lane & 3;
    int wid = tid >> 5;               // 0..15
    int wm = (wid & 3) * 32;
    int wn = (wid >> 2) * 32;
    int nc = (ke - kb) >> 4;

    uint32_t sbase = smem_addr_u32(sm);
    uint32_t dA = sbase + (uint32_t)(rowL*PADK + koff)*4u;
    uint32_t dW = sbase + (uint32_t)((128 + rowL)*PADK + koff)*4u;
    const float* Ag = A + (size_t)(bm + rowL)*HIDDEN + kb + koff;
    const float* Wg = W + (size_t)(bn + rowL)*HIDDEN + kb + koff;

#define ISSUE(c) do { \
    uint32_t off_ = (uint32_t)((c) & (NSTAGE-1)) * (STAGE_WORDS*4u); \
    cp_async16(dA + off_, Ag + ((c) << 4)); \
    cp_async16(dW + off_, Wg + ((c) << 4)); \
    cp_commit(); \
} while(0)

#define LOAD_FRAGS(buf, c) do { \
    const unsigned (*As_)[PADK] = (const unsigned (*)[PADK])(sm + (size_t)((c) & (NSTAGE-1))*STAGE_WORDS); \
    const unsigned (*Ws_)[PADK] = As_ + 128; \
    _Pragma("unroll") \
    for (int h = 0; h < 2; h++) { \
        int s8 = h * 8; \
        _Pragma("unroll") \
        for (int j = 0; j < 4; j++) { \
            bf[buf][h][j][0] = Ws_[wn + 8*j + q][s8 + r]; \
            bf[buf][h][j][1] = Ws_[wn + 8*j + q][s8 + 4 + r]; \
        } \
        _Pragma("unroll") \
        for (int t = 0; t < 2; t++) { \
            af[buf][h][t][0] = As_[wm + 16*t + q][s8 + r]; \
            af[buf][h][t][1] = As_[wm + 16*t + 8 + q][s8 + r]; \
            af[buf][h][t][2] = As_[wm + 16*t + q][s8 + 4 + r]; \
            af[buf][h][t][3] = As_[wm + 16*t + 8 + q][s8 + 4 + r]; \
        } \
    } \
} while(0)

    unsigned bf[2][2][4][2], af[2][2][2][4];

    // prologue: 3 groups outstanding; load frags of chunk 0
    ISSUE(0);
    if (nc > 1) ISSUE(1); else cp_commit();
    if (nc > 2) ISSUE(2); else cp_commit();
    cp_wait<2>();               // chunk 0 complete
    __syncthreads();
    LOAD_FRAGS(0, 0);

    int cur = 0;
    for (int c = 0; c < nc; c++) {
        if (c + 3 < nc) ISSUE(c + 3); else cp_commit();
        if (c + 1 < nc) {
            cp_wait<2>();       // chunks <= c+1 complete
            __syncthreads();    // all threads' copies visible; also fences prior frag reads vs ISSUE
            LOAD_FRAGS(cur ^ 1, c + 1);
        }
        // MMAs for chunk c — fragments already in registers, no smem dependence
        #pragma unroll
        for (int h = 0; h < 2; h++)
            #pragma unroll
            for (int t = 0; t < 2; t++)
                #pragma unroll
                for (int j = 0; j < 4; j++)
                    mma_tf32(d[t][j], af[cur][h][t], bf[cur][h][j]);
        cur ^= 1;
    }
    __syncthreads();            // protect stage reuse by a following pass
#undef ISSUE
#undef LOAD_FRAGS
}

// ---------------- layer-0 projection: [NT,6] @ [512,6]^T + bih0 -> enc_out region ----------------
__global__ void __launch_bounds__(512) proj0_kernel(const float* __restrict__ x,
    const float* __restrict__ W, const float* __restrict__ bias, float* __restrict__ out)
{
    __shared__ float Ws[HIDDEN*INDIM];
    __shared__ float bs[HIDDEN];
    __shared__ float xs[32][INDIM];
    int tid = threadIdx.x;
    for (int i = tid; i < HIDDEN*INDIM; i += 512) Ws[i] = W[i];
    if (tid < HIDDEN) bs[tid] = bias[tid];
    int r0 = blockIdx.x * 32;
    if (tid < 32*INDIM) xs[tid/INDIM][tid%INDIM] = x[(size_t)(r0 + tid/INDIM)*INDIM + tid%INDIM];
    __syncthreads();
    int h = tid;
    #pragma unroll 4
    for (int r = 0; r < 32; r++) {
        float acc = bs[h];
        #pragma unroll
        for (int d = 0; d < INDIM; d++) acc += xs[r][d] * Ws[h*INDIM + d];
        out[(size_t)(r0 + r)*HIDDEN + h] = acc;
    }
}

// ---------------- encoder wavefront superstep ----------------
__global__ void __launch_bounds__(512, 1) wave_step(
    int s,
    const float* __restrict__ wr,
    const float* __restrict__ ebih, const float* __restrict__ ebhh,
    float* __restrict__ hb, float* __restrict__ enc_out)
{
    int l = blockIdx.z;
    int ts = s - l;
    if (ts < 0 || ts >= SEQT) return;
    int p_r = (s + 1) & 1, p_w = s & 1;

    extern __shared__ unsigned sm[];
    int tid = threadIdx.x;
    int bm = blockIdx.x * 128, bn = blockIdx.y * 128;

    float d[2][4][4];
    #pragma unroll
    for (int t = 0; t < 2; t++)
        #pragma unroll
        for (int j = 0; j < 4; j++)
            #pragma unroll
            for (int c = 0; c < 4; c++) d[t][j][c] = 0.f;

    const float* eWih = wr;
    const float* eWhh = wr + 3*(size_t)HH;
    if (l == 0) {
        gemm_tf32(hb + (size_t)p_r*BH, eWhh, 0, HIDDEN, bm, bn, tid, sm, d);
    } else {
        gemm_tf32(hb + ((size_t)(l-1)*2 + p_r)*BH, eWih + (size_t)(l-1)*HH, 0, HIDDEN, bm, bn, tid, sm, d);
        gemm_tf32(hb + ((size_t)l*2 + p_r)*BH,     eWhh + (size_t)l*HH,     0, HIDDEN, bm, bn, tid, sm, d);
    }

    int lane = tid & 31;
    int q = lane >> 2, r = lane & 3;
    int wid = tid >> 5;
    int wm = (wid & 3) * 32;
    int wn = (wid >> 2) * 32;
    float* hout = hb + ((size_t)l*2 + p_w)*BH;

    #pragma unroll
    for (int j = 0; j < 4; j++) {
        int c = bn + wn + 8*j + 2*r;
        float b0 = ebhh[l*HIDDEN + c], b1 = ebhh[l*HIDDEN + c + 1];
        if (l > 0) { b0 += ebih[l*HIDDEN + c]; b1 += ebih[l*HIDDEN + c + 1]; }
        #pragma unroll
        for (int t = 0; t < 2; t++) {
            int ra = bm + wm + 16*t + q;
            int rb = ra + 8;
            float v0 = d[t][j][0] + b0, v1 = d[t][j][1] + b1;
            float v2 = d[t][j][2] + b0, v3 = d[t][j][3] + b1;
            if (l == 0) {
                const float* xa = enc_out + ((size_t)ra*SEQT + ts)*HIDDEN + c;
                const float* xb = enc_out + ((size_t)rb*SEQT + ts)*HIDDEN + c;
                float2 pa = *(const float2*)xa;
                float2 pb = *(const float2*)xb;
                v0 += pa.x; v1 += pa.y; v2 += pb.x; v3 += pb.y;
            }
            v0 = fast_tanh(v0); v1 = fast_tanh(v1);
            v2 = fast_tanh(v2); v3 = fast_tanh(v3);
            *(float2*)(hout + (size_t)ra*HIDDEN + c) = make_float2(round_tf32f(v0), round_tf32f(v1));
            *(float2*)(hout + (size_t)rb*HIDDEN + c) = make_float2(round_tf32f(v2), round_tf32f(v3));
            if (l == 3) {
                *(float2*)(enc_out + ((size_t)ra*SEQT + ts)*HIDDEN + c) = make_float2(v0, v1);
                *(float2*)(enc_out + ((size_t)rb*SEQT + ts)*HIDDEN + c) = make_float2(v2, v3);
            }
        }
    }
}

// ---------------- decoder split-K partial ----------------
__global__ void __launch_bounds__(512, 1) dec_partial(
    const float* __restrict__ xin, const float* __restrict__ Wih,
    const float* __restrict__ hin, const float* __restrict__ Whh,
    float* __restrict__ part)
{
    extern __shared__ unsigned sm[];
    int tid = threadIdx.x;
    int bm = blockIdx.x * 128, bn = blockIdx.y * 128;
    int z = blockIdx.z;

    float d[2][4][4];
    #pragma unroll
    for (int t = 0; t < 2; t++)
        #pragma unroll
        for (int j = 0; j < 4; j++)
            #pragma unroll
            for (int c = 0; c < 4; c++) d[t][j][c] = 0.f;

    const float* A = (z >> 1) ? hin : xin;
    const float* W = (z >> 1) ? Whh : Wih;
    int kb = (z & 1) * 256;
    gemm_tf32(A, W, kb, kb + 256, bm, bn, tid, sm, d);

    int lane = tid & 31;
    int q = lane >> 2, r = lane & 3;
    int wid = tid >> 5;
    int wm = (wid & 3) * 32;
    int wn = (wid >> 2) * 32;
    float* dst = part + (size_t)z*BH;

    #pragma unroll
    for (int j = 0; j < 4; j++) {
        int c = bn + wn + 8*j + 2*r;
        #pragma unroll
        for (int t = 0; t < 2; t++) {
            int ra = bm + wm + 16*t + q;
            int rb = ra + 8;
            *(float2*)(dst + (size_t)ra*HIDDEN + c) = make_float2(d[t][j][0], d[t][j][1]);
            *(float2*)(dst + (size_t)rb*HIDDEN + c) = make_float2(d[t][j][2], d[t][j][3]);
        }
    }
}

// ---------------- decoder reduce: h = tanh(sum parts + bih + bhh) ----------------
__global__ void __launch_bounds__(256) dec_reduce(
    const float* __restrict__ part, const float* __restrict__ bih, const float* __restrict__ bhh,
    float* __restrict__ hout, float* __restrict__ dout)
{
    int e = blockIdx.x * blockDim.x + threadIdx.x;
    int n = (e & 127) * 4;
    int m = e >> 7;
    size_t off = (size_t)e * 4;
    float4 s0 = *(const float4*)(part + off);
    float4 s1 = *(const float4*)(part + BH + off);
    float4 s2 = *(const float4*)(part + 2*(size_t)BH + off);
    float4 s3 = *(const float4*)(part + 3*(size_t)BH + off);
    float4 b1 = *(const float4*)(bih + n);
    float4 b2 = *(const float4*)(bhh + n);
    float4 v;
    v.x = fast_tanh(s0.x + s1.x + s2.x + s3.x + b1.x + b2.x);
    v.y = fast_tanh(s0.y + s1.y + s2.y + s3.y + b1.y + b2.y);
    v.z = fast_tanh(s0.z + s1.z + s2.z + s3.z + b1.z + b2.z);
    v.w = fast_tanh(s0.w + s1.w + s2.w + s3.w + b1.w + b2.w);
    float4 vr;
    vr.x = round_tf32f(v.x); vr.y = round_tf32f(v.y);
    vr.z = round_tf32f(v.z); vr.w = round_tf32f(v.w);
    *(float4*)(hout + off) = vr;
    if (dout) *(float4*)(dout + (size_t)m*PRED*HIDDEN + n) = v;
}

// ---------------- final FC: [B*PRED,512] @ [6,512]^T + b ----------------
__global__ void __launch_bounds__(256) fc_kernel(const float* __restrict__ X,
    const float* __restrict__ W, const float* __restrict__ bias, float* __restrict__ out)
{
    __shared__ float Ws[OUTDIM][HIDDEN];
    int tid = threadIdx.x;
    for (int i = tid; i < OUTDIM*HIDDEN; i += 256) Ws[i/HIDDEN][i%HIDDEN] = W[i];
    __syncthreads();
    int warp = tid >> 5, lane = tid & 31;
    int row = blockIdx.x*8 + warp;
    float s[OUTDIM];
    #pragma unroll
    for (int o = 0; o < OUTDIM; o++) s[o] = 0.f;
    for (int k = lane; k < HIDDEN; k += 32) {
        float xv = X[(size_t)row*HIDDEN + k];
        #pragma unroll
        for (int o = 0; o < OUTDIM; o++) s[o] += xv * Ws[o][k];
    }
    #pragma unroll
    for (int o = 0; o < OUTDIM; o++) {
        #pragma unroll
        for (int off = 16; off; off >>= 1) s[o] += __shfl_down_sync(0xffffffffu, s[o], off);
    }
    if (lane == 0) {
        #pragma unroll
        for (int o = 0; o < OUTDIM; o++) out[(size_t)row*OUTDIM + o] = s[o] + bias[o];
    }
}

extern "C" void kernel_launch(void* const* d_in, const int* in_sizes, int n_in,
                              void* d_out, int out_size)
{
    (void)in_sizes; (void)n_in; (void)out_size;
    const float* x     = (const float*)d_in[0];
    const float* eWih0 = (const float*)d_in[1];
    const float* eWih  = (const float*)d_in[2];
    const float* eWhh  = (const float*)d_in[3];
    const float* ebih  = (const float*)d_in[4];
    const float* ebhh  = (const float*)d_in[5];
    const float* dWih  = (const float*)d_in[6];
    const float* dWhh  = (const float*)d_in[7];
    const float* dbih  = (const float*)d_in[8];
    const float* dbhh  = (const float*)d_in[9];
    const float* fcW   = (const float*)d_in[10];
    const float* fcb   = (const float*)d_in[11];

    float* out = (float*)d_out;
    float* enc_out = out;
    float* dec_final = out + (size_t)ENC_ELEMS;

    float *hb, *hd, *part, *dout, *wr;
    cudaGetSymbolAddress((void**)&hb,   g_h);
    cudaGetSymbolAddress((void**)&hd,   g_hd);
    cudaGetSymbolAddress((void**)&part, g_part);
    cudaGetSymbolAddress((void**)&dout, g_decout);
    cudaGetSymbolAddress((void**)&wr,   g_wr);

    static bool attr_set = false;
    if (!attr_set) {
        cudaFuncSetAttribute(wave_step,  cudaFuncAttributeMaxDynamicSharedMemorySize, SMEM_BYTES);
        cudaFuncSetAttribute(dec_partial, cudaFuncAttributeMaxDynamicSharedMemorySize, SMEM_BYTES);
        attr_set = true;
    }

    // pre-round all 15 weight matrices to tf32 in ONE launch
    round_weights_all<<<(15*HH/4 + 255)/256, 256>>>(
        (const float4*)eWih, (const float4*)eWhh,
        (const float4*)dWih, (const float4*)dWhh, (float4*)wr);

    cudaMemsetAsync(hb, 0, (size_t)NLAYER*2*BH*sizeof(float), 0);

    proj0_kernel<<<NT/32, 512>>>(x, eWih0, ebih, enc_out);

    dim3 wg(BATCH/128, HIDDEN/128, NLAYER);
    for (int s = 0; s < SEQT + NLAYER - 1; s++)
        wave_step<<<wg, 512, SMEM_BYTES>>>(s, wr, ebih, ebhh, hb, enc_out);

    const float* wr_dWih = wr + 7*(size_t)HH;
    const float* wr_dWhh = wr + 11*(size_t)HH;
    dim3 dg(BATCH/128, HIDDEN/128, 4);
    for (int p = 0; p < PRED; p++) {
        float* hdcur  = hd + (size_t)(p & 1)*NLAYER*BH;
        float* hdprev = hd + (size_t)((p + 1) & 1)*NLAYER*BH;
        for (int l = 0; l < NLAYER; l++) {
            const float* xin = (l == 0)
                ? ((p == 0) ? hb + ((size_t)3*2 + 0)*BH
                            : hdprev + (size_t)3*BH)
                : hdcur + (size_t)(l-1)*BH;
            const float* hin = (p == 0)
                ? hb + ((size_t)l*2 + ((127 + l) & 1))*BH
                : hdprev + (size_t)l*BH;
            dec_partial<<<dg, 512, SMEM_BYTES>>>(xin, wr_dWih + (size_t)l*HH, hin, wr_dWhh + (size_t)l*HH, part);
            dec_reduce<<<BH/4/256, 256>>>(part, dbih + l*HIDDEN, dbhh + l*HIDDEN,
                                          hdcur + (size_t)l*BH,
                                          (l == NLAYER-1) ? (dout + (size_t)p*HIDDEN) : nullptr);
        }
    }

    fc_kernel<<<BATCH*PRED/8, 256>>>(dout, fcW, fcb, dec_final);
}

// round 14
// speedup vs baseline: 2.4328x; 2.4328x over previous
#include <cuda_runtime.h>
#include <math.h>
#include <stdint.h>

#define BATCH 1024
#define SEQT 128
#define HIDDEN 512
#define HH (HIDDEN*HIDDEN)
#define BH (BATCH*HIDDEN)
#define NLAYER 4
#define PRED 10
#define INDIM 6
#define OUTDIM 6
#define NT (BATCH*SEQT)
#define ENC_ELEMS (NT*HIDDEN)
#define PADK 20

// ---------------- scratch (device globals; no allocation allowed) ----------------
__device__ float g_h[NLAYER*2*BH];            // encoder hidden ping-pong [layer][parity][B*H]
__device__ float g_hd[2*NLAYER*BH];           // decoder hidden ping-pong [parity][layer][B*H]
__device__ float g_part[4*BH];                // split-K partials
__device__ float g_decout[BATCH*PRED*HIDDEN]; // decoder outputs for FC

// ---------------- tf32 helpers ----------------
__device__ __forceinline__ unsigned cvt_tf32(float v){
    unsigned r; asm("cvt.rna.tf32.f32 %0, %1;" : "=r"(r) : "f"(v)); return r;
}
__device__ __forceinline__ void mma_tf32(float* d, const unsigned* a, const unsigned* b){
    asm volatile(
        "mma.sync.aligned.m16n8k8.row.col.f32.tf32.tf32.f32 "
        "{%0,%1,%2,%3}, {%4,%5,%6,%7}, {%8,%9}, {%0,%1,%2,%3};"
        : "+f"(d[0]), "+f"(d[1]), "+f"(d[2]), "+f"(d[3])
        : "r"(a[0]), "r"(a[1]), "r"(a[2]), "r"(a[3]), "r"(b[0]), "r"(b[1]));
}

// ---------------- MUFU-free tanh ----------------
__device__ __forceinline__ float fast_tanh(float x){
    float cx = fminf(fmaxf(x, -9.5f), 9.5f);
    float z  = cx * 2.8853900818f;               // 2x * log2(e)
    float y  = z + 12582912.0f;                  // round to nearest int
    int   n  = __float_as_int(y) - 0x4B400000;
    float f  = z - (y - 12582912.0f);            // [-0.5, 0.5]
    float t = 1.5252733e-05f;
    t = fmaf(t, f, 1.5403530e-04f);
    t = fmaf(t, f, 1.3333558e-03f);
    t = fmaf(t, f, 9.6181291e-03f);
    t = fmaf(t, f, 5.5504109e-02f);
    t = fmaf(t, f, 2.4022651e-01f);
    t = fmaf(t, f, 6.9314718e-01f);
    t = t * f;                                   // 2^f - 1
    float s   = __int_as_float((n + 127) << 23);
    float em1 = fmaf(s, t, s - 1.0f);            // e^{2x} - 1
    float ep1 = em1 + 2.0f;
    float r = __int_as_float(0x7EF311C3 - __float_as_int(ep1));
    r = r * fmaf(-ep1, r, 2.0f);
    r = r * fmaf(-ep1, r, 2.0f);
    r = r * fmaf(-ep1, r, 2.0f);
    return em1 * r;
}

// ---------------- tf32 tensor-core GEMM pass (512 thr, double-buffer, 1 sync/chunk) ----------------
// acc += A[bm:bm+128, kb:ke] @ W[bn:bn+128, kb:ke]^T   (both row-major [*, 512])
// 16 warps in 4x4 grid; warp tile 32x32: 2 m16 x 4 n8 MMAs per k8.
// Per chunk c: LDG(c+1) -> frag LDS from buf c&1 -> MMA h0 -> STS buf (c+1)&1 -> MMA h1 -> sync.
// Hazards: STS(c+1) vs reads of buf (c+1)&1 (iter c-1) are separated by iter c-1's sync;
// reads of buf c&1 (iter c) vs STS(c+2) (iter c+1) are separated by iter c's sync.
__device__ __forceinline__ void gemm_tf32(
    const float* __restrict__ A, const float* __restrict__ W,
    int kb, int ke, int bm, int bn, int tid,
    unsigned (*As)[128][PADK], unsigned (*Ws)[128][PADK], float (*d)[4][4])
{
    int rowL = tid >> 2;              // 0..127
    int koff = (tid & 3) << 2;        // 0,4,8,12
    int lane = tid & 31;
    int q = lane >> 2, r = lane & 3;
    int wid = tid >> 5;               // 0..15
    int wm = (wid & 3) * 32;
    int wn = (wid >> 2) * 32;
    int nc = (ke - kb) >> 4;

    const float* Ag = A + (size_t)(bm + rowL)*HIDDEN + kb + koff;
    const float* Wg = W + (size_t)(bn + rowL)*HIDDEN + kb + koff;

    float4 a0 = *(const float4*)Ag;
    float4 w0 = *(const float4*)Wg;

#define STS_CHUNK(b) do { \
    uint4 av_, wv_; \
    av_.x = cvt_tf32(a0.x); av_.y = cvt_tf32(a0.y); av_.z = cvt_tf32(a0.z); av_.w = cvt_tf32(a0.w); \
    wv_.x = cvt_tf32(w0.x); wv_.y = cvt_tf32(w0.y); wv_.z = cvt_tf32(w0.z); wv_.w = cvt_tf32(w0.w); \
    *(uint4*)&As[b][rowL][koff] = av_; \
    *(uint4*)&Ws[b][rowL][koff] = wv_; \
} while(0)

    STS_CHUNK(0);
    __syncthreads();

    for (int c = 0; c < nc; c++) {
        bool more = (c + 1 < nc);
        if (more) {                     // gmem prefetch for chunk c+1
            a0 = *(const float4*)(Ag + ((c + 1) << 4));
            w0 = *(const float4*)(Wg + ((c + 1) << 4));
        }
        const unsigned (*Ab)[PADK] = As[c & 1];
        const unsigned (*Wb)[PADK] = Ws[c & 1];

        // all fragments of current chunk into registers (statically indexed arrays)
        unsigned bf[2][4][2], af[2][2][4];
        #pragma unroll
        for (int h = 0; h < 2; h++) {
            int s8 = h * 8;
            #pragma unroll
            for (int j = 0; j < 4; j++) {
                bf[h][j][0] = Wb[wn + 8*j + q][s8 + r];
                bf[h][j][1] = Wb[wn + 8*j + q][s8 + 4 + r];
            }
            #pragma unroll
            for (int t = 0; t < 2; t++) {
                af[h][t][0] = Ab[wm + 16*t + q][s8 + r];
                af[h][t][1] = Ab[wm + 16*t + 8 + q][s8 + r];
                af[h][t][2] = Ab[wm + 16*t + q][s8 + 4 + r];
                af[h][t][3] = Ab[wm + 16*t + 8 + q][s8 + 4 + r];
            }
        }
        #pragma unroll
        for (int t = 0; t < 2; t++)     // MMA half 0
            #pragma unroll
            for (int j = 0; j < 4; j++)
                mma_tf32(d[t][j], af[0][t], bf[0][j]);
        if (more) STS_CHUNK((c + 1) & 1);   // fill other buffer while tensor pipe busy
        #pragma unroll
        for (int t = 0; t < 2; t++)     // MMA half 1
            #pragma unroll
            for (int j = 0; j < 4; j++)
                mma_tf32(d[t][j], af[1][t], bf[1][j]);
        __syncthreads();                // single barrier per chunk
    }
#undef STS_CHUNK
}

// ---------------- layer-0 projection: [NT,6] @ [512,6]^T + bih0 -> enc_out region ----------------
__global__ void __launch_bounds__(512) proj0_kernel(const float* __restrict__ x,
    const float* __restrict__ W, const float* __restrict__ bias, float* __restrict__ out)
{
    __shared__ float Ws[HIDDEN*INDIM];
    __shared__ float bs[HIDDEN];
    __shared__ float xs[32][INDIM];
    int tid = threadIdx.x;
    for (int i = tid; i < HIDDEN*INDIM; i += 512) Ws[i] = W[i];
    if (tid < HIDDEN) bs[tid] = bias[tid];
    int r0 = blockIdx.x * 32;
    if (tid < 32*INDIM) xs[tid/INDIM][tid%INDIM] = x[(size_t)(r0 + tid/INDIM)*INDIM + tid%INDIM];
    __syncthreads();
    int h = tid;
    #pragma unroll 4
    for (int r = 0; r < 32; r++) {
        float acc = bs[h];
        #pragma unroll
        for (int d = 0; d < INDIM; d++) acc += xs[r][d] * Ws[h*INDIM + d];
        out[(size_t)(r0 + r)*HIDDEN + h] = acc;
    }
}

// ---------------- encoder wavefront superstep (tf32 tensor core, 512 thr) ----------------
// blockIdx.z = layer l; computes ts = s - l.
__global__ void __launch_bounds__(512, 1) wave_step(
    int s,
    const float* __restrict__ eWih, const float* __restrict__ eWhh,
    const float* __restrict__ ebih, const float* __restrict__ ebhh,
    float* __restrict__ hb, float* __restrict__ enc_out)
{
    int l = blockIdx.z;
    int ts = s - l;
    if (ts < 0 || ts >= SEQT) return;
    int p_r = (s + 1) & 1, p_w = s & 1;

    __shared__ __align__(16) unsigned As[2][128][PADK];
    __shared__ __align__(16) unsigned Ws[2][128][PADK];
    int tid = threadIdx.x;
    int bm = blockIdx.x * 128, bn = blockIdx.y * 128;

    float d[2][4][4];
    #pragma unroll
    for (int t = 0; t < 2; t++)
        #pragma unroll
        for (int j = 0; j < 4; j++)
            #pragma unroll
            for (int c = 0; c < 4; c++) d[t][j][c] = 0.f;

    if (l == 0) {
        gemm_tf32(hb + (size_t)p_r*BH, eWhh, 0, HIDDEN, bm, bn, tid, As, Ws, d);
    } else {
        gemm_tf32(hb + ((size_t)(l-1)*2 + p_r)*BH, eWih + (size_t)(l-1)*HH, 0, HIDDEN, bm, bn, tid, As, Ws, d);
        gemm_tf32(hb + ((size_t)l*2 + p_r)*BH,     eWhh + (size_t)l*HH,     0, HIDDEN, bm, bn, tid, As, Ws, d);
    }

    int lane = tid & 31;
    int q = lane >> 2, r = lane & 3;
    int wid = tid >> 5;
    int wm = (wid & 3) * 32;
    int wn = (wid >> 2) * 32;
    float* hout = hb + ((size_t)l*2 + p_w)*BH;

    #pragma unroll
    for (int j = 0; j < 4; j++) {
        int c = bn + wn + 8*j + 2*r;
        float b0 = ebhh[l*HIDDEN + c], b1 = ebhh[l*HIDDEN + c + 1];
        if (l > 0) { b0 += ebih[l*HIDDEN + c]; b1 += ebih[l*HIDDEN + c + 1]; }
        #pragma unroll
        for (int t = 0; t < 2; t++) {
            int ra = bm + wm + 16*t + q;
            int rb = ra + 8;
            float v0 = d[t][j][0] + b0, v1 = d[t][j][1] + b1;
            float v2 = d[t][j][2] + b0, v3 = d[t][j][3] + b1;
            if (l == 0) {
                const float* xa = enc_out + ((size_t)ra*SEQT + ts)*HIDDEN + c;
                const float* xb = enc_out + ((size_t)rb*SEQT + ts)*HIDDEN + c;
                float2 pa = *(const float2*)xa;
                float2 pb = *(const float2*)xb;
                v0 += pa.x; v1 += pa.y; v2 += pb.x; v3 += pb.y;
            }
            v0 = fast_tanh(v0); v1 = fast_tanh(v1);
            v2 = fast_tanh(v2); v3 = fast_tanh(v3);
            *(float2*)(hout + (size_t)ra*HIDDEN + c) = make_float2(v0, v1);
            *(float2*)(hout + (size_t)rb*HIDDEN + c) = make_float2(v2, v3);
            if (l == 3) {
                *(float2*)(enc_out + ((size_t)ra*SEQT + ts)*HIDDEN + c) = make_float2(v0, v1);
                *(float2*)(enc_out + ((size_t)rb*SEQT + ts)*HIDDEN + c) = make_float2(v2, v3);
            }
        }
    }
}

// ---------------- decoder split-K partial (tf32, 512 thr) ----------------
__global__ void __launch_bounds__(512, 1) dec_partial(
    const float* __restrict__ xin, const float* __restrict__ Wih,
    const float* __restrict__ hin, const float* __restrict__ Whh,
    float* __restrict__ part)
{
    __shared__ __align__(16) unsigned As[2][128][PADK];
    __shared__ __align__(16) unsigned Ws[2][128][PADK];
    int tid = threadIdx.x;
    int bm = blockIdx.x * 128, bn = blockIdx.y * 128;
    int z = blockIdx.z;

    float d[2][4][4];
    #pragma unroll
    for (int t = 0; t < 2; t++)
        #pragma unroll
        for (int j = 0; j < 4; j++)
            #pragma unroll
            for (int c = 0; c < 4; c++) d[t][j][c] = 0.f;

    const float* A = (z >> 1) ? hin : xin;
    const float* W = (z >> 1) ? Whh : Wih;
    int kb = (z & 1) * 256;
    gemm_tf32(A, W, kb, kb + 256, bm, bn, tid, As, Ws, d);

    int lane = tid & 31;
    int q = lane >> 2, r = lane & 3;
    int wid = tid >> 5;
    int wm = (wid & 3) * 32;
    int wn = (wid >> 2) * 32;
    float* dst = part + (size_t)z*BH;

    #pragma unroll
    for (int j = 0; j < 4; j++) {
        int c = bn + wn + 8*j + 2*r;
        #pragma unroll
        for (int t = 0; t < 2; t++) {
            int ra = bm + wm + 16*t + q;
            int rb = ra + 8;
            *(float2*)(dst + (size_t)ra*HIDDEN + c) = make_float2(d[t][j][0], d[t][j][1]);
            *(float2*)(dst + (size_t)rb*HIDDEN + c) = make_float2(d[t][j][2], d[t][j][3]);
        }
    }
}

// ---------------- decoder reduce: h = tanh(sum parts + bih + bhh) ----------------
__global__ void __launch_bounds__(256) dec_reduce(
    const float* __restrict__ part, const float* __restrict__ bih, const float* __restrict__ bhh,
    float* __restrict__ hout, float* __restrict__ dout)
{
    int e = blockIdx.x * blockDim.x + threadIdx.x;   // float4 index over BH/4
    int n = (e & 127) * 4;
    int m = e >> 7;
    size_t off = (size_t)e * 4;
    float4 s0 = *(const float4*)(part + off);
    float4 s1 = *(const float4*)(part + BH + off);
    float4 s2 = *(const float4*)(part + 2*(size_t)BH + off);
    float4 s3 = *(const float4*)(part + 3*(size_t)BH + off);
    float4 b1 = *(const float4*)(bih + n);
    float4 b2 = *(const float4*)(bhh + n);
    float4 v;
    v.x = fast_tanh(s0.x + s1.x + s2.x + s3.x + b1.x + b2.x);
    v.y = fast_tanh(s0.y + s1.y + s2.y + s3.y + b1.y + b2.y);
    v.z = fast_tanh(s0.z + s1.z + s2.z + s3.z + b1.z + b2.z);
    v.w = fast_tanh(s0.w + s1.w + s2.w + s3.w + b1.w + b2.w);
    *(float4*)(hout + off) = v;
    if (dout) *(float4*)(dout + (size_t)m*PRED*HIDDEN + n) = v;
}

// ---------------- final FC: [B*PRED,512] @ [6,512]^T + b ----------------
__global__ void __launch_bounds__(256) fc_kernel(const float* __restrict__ X,
    const float* __restrict__ W, const float* __restrict__ bias, float* __restrict__ out)
{
    __shared__ float Ws[OUTDIM][HIDDEN];
    int tid = threadIdx.x;
    for (int i = tid; i < OUTDIM*HIDDEN; i += 256) Ws[i/HIDDEN][i%HIDDEN] = W[i];
    __syncthreads();
    int warp = tid >> 5, lane = tid & 31;
    int row = blockIdx.x*8 + warp;
    float s[OUTDIM];
    #pragma unroll
    for (int o = 0; o < OUTDIM; o++) s[o] = 0.f;
    for (int k = lane; k < HIDDEN; k += 32) {
        float xv = X[(size_t)row*HIDDEN + k];
        #pragma unroll
        for (int o = 0; o < OUTDIM; o++) s[o] += xv * Ws[o][k];
    }
    #pragma unroll
    for (int o = 0; o < OUTDIM; o++) {
        #pragma unroll
        for (int off = 16; off; off >>= 1) s[o] += __shfl_down_sync(0xffffffffu, s[o], off);
    }
    if (lane == 0) {
        #pragma unroll
        for (int o = 0; o < OUTDIM; o++) out[(size_t)row*OUTDIM + o] = s[o] + bias[o];
    }
}

extern "C" void kernel_launch(void* const* d_in, const int* in_sizes, int n_in,
                              void* d_out, int out_size)
{
    (void)in_sizes; (void)n_in; (void)out_size;
    const float* x     = (const float*)d_in[0];
    const float* eWih0 = (const float*)d_in[1];
    const float* eWih  = (const float*)d_in[2];
    const float* eWhh  = (const float*)d_in[3];
    const float* ebih  = (const float*)d_in[4];
    const float* ebhh  = (const float*)d_in[5];
    const float* dWih  = (const float*)d_in[6];
    const float* dWhh  = (const float*)d_in[7];
    const float* dbih  = (const float*)d_in[8];
    const float* dbhh  = (const float*)d_in[9];
    const float* fcW   = (const float*)d_in[10];
    const float* fcb   = (const float*)d_in[11];

    float* out = (float*)d_out;
    float* enc_out = out;                             // [B, T, H] (staging for xw0, final enc output)
    float* dec_final = out + (size_t)ENC_ELEMS;       // [B, PRED, OUT]

    float *hb, *hd, *part, *dout;
    cudaGetSymbolAddress((void**)&hb,   g_h);
    cudaGetSymbolAddress((void**)&hd,   g_hd);
    cudaGetSymbolAddress((void**)&part, g_part);
    cudaGetSymbolAddress((void**)&dout, g_decout);

    // zero all encoder hidden ping-pong buffers (initial h_{-1} = 0 for every parity)
    cudaMemsetAsync(hb, 0, (size_t)NLAYER*2*BH*sizeof(float), 0);

    // layer-0 input projection (includes bih0) staged into enc_out
    proj0_kernel<<<NT/32, 512>>>(x, eWih0, ebih, enc_out);

    // encoder wavefront: supersteps s = 0 .. SEQT+NLAYER-2
    dim3 wg(BATCH/128, HIDDEN/128, NLAYER);   // 8 x 4 x 4
    for (int s = 0; s < SEQT + NLAYER - 1; s++)
        wave_step<<<wg, 512>>>(s, eWih, eWhh, ebih, ebhh, hb, enc_out);

    // decoder: 10 steps x 4 layers, split-K partial + reduce
    dim3 dg(BATCH/128, HIDDEN/128, 4);        // 8 x 4 x 4
    for (int p = 0; p < PRED; p++) {
        float* hdcur  = hd + (size_t)(p & 1)*NLAYER*BH;
        float* hdprev = hd + (size_t)((p + 1) & 1)*NLAYER*BH;
        for (int l = 0; l < NLAYER; l++) {
            const float* xin = (l == 0)
                ? ((p == 0) ? hb + ((size_t)3*2 + 0)*BH          // h_{3,T-1} parity (127+3)&1=0
                            : hdprev + (size_t)3*BH)
                : hdcur + (size_t)(l-1)*BH;
            const float* hin = (p == 0)
                ? hb + ((size_t)l*2 + ((127 + l) & 1))*BH        // encoder final hidden of layer l
                : hdprev + (size_t)l*BH;
            dec_partial<<<dg, 512>>>(xin, dWih + (size_t)l*HH, hin, dWhh + (size_t)l*HH, part);
            dec_reduce<<<BH/4/256, 256>>>(part, dbih + l*HIDDEN, dbhh + l*HIDDEN,
                                          hdcur + (size_t)l*BH,
                                          (l == NLAYER-1) ? (dout + (size_t)p*HIDDEN) : nullptr);
        }
    }

    // final FC
    fc_kernel<<<BATCH*PRED/8, 256>>>(dout, fcW, fcb, dec_final);
}